// round 4
// baseline (speedup 1.0000x reference)
#include <cuda_runtime.h>
#include <cstdint>

#define M_V 50000   // vocab
#define N_F 1000    // filters
#define K_D 300     // embedding dim
#define B_B 128
#define L_L 512

// 200 MB scratch: vocab x filter score table S[v,f], row stride 1000
__device__ float g_S[(size_t)M_V * N_F];
// phase-2 partial token contributions [2 splits][B][L]
__device__ float g_P[2 * B_B * L_L];

#define BM 128
#define BN 128
#define BK 16
#define LDU2 20          // uint2 row stride: conflict-free LDS.64 frag loads
#define NCHUNK 19        // ceil(300/16)
#define STAGE_U2 (2 * BM * LDU2)          // A tile + B tile per stage (uint2)
#define SMEM_BYTES (2 * STAGE_U2 * 8)     // 81920

__device__ __forceinline__ uint32_t f2tf32(float x) {
    uint32_t u;
    asm("cvt.rna.tf32.f32 %0, %1;" : "=r"(u) : "f"(x));
    return u;
}

__device__ __forceinline__ void mma8(float* c, const uint32_t* a, const uint32_t* b) {
    asm volatile(
        "mma.sync.aligned.m16n8k8.row.col.f32.tf32.tf32.f32 "
        "{%0,%1,%2,%3}, {%4,%5,%6,%7}, {%8,%9}, {%0,%1,%2,%3};"
        : "+f"(c[0]), "+f"(c[1]), "+f"(c[2]), "+f"(c[3])
        : "r"(a[0]), "r"(a[1]), "r"(a[2]), "r"(a[3]), "r"(b[0]), "r"(b[1]));
}

// split float4 -> two uint4 {h0,l0,h1,l1},{h2,l2,h3,l3} (hi/lo interleaved)
__device__ __forceinline__ void split_store(uint2* dst, float4 v) {
    uint32_t h0 = f2tf32(v.x), h1 = f2tf32(v.y), h2 = f2tf32(v.z), h3 = f2tf32(v.w);
    uint32_t l0 = f2tf32(v.x - __uint_as_float(h0));
    uint32_t l1 = f2tf32(v.y - __uint_as_float(h1));
    uint32_t l2 = f2tf32(v.z - __uint_as_float(h2));
    uint32_t l3 = f2tf32(v.w - __uint_as_float(h3));
    *(uint4*)(dst)     = make_uint4(h0, l0, h1, l1);
    *(uint4*)(dst + 2) = make_uint4(h2, l2, h3, l3);
}

// ===========================================================================
// Phase 1: S[v,f] = emb[v,:] . conv_w[f,:]  via 3xTF32 mma.sync GEMM (NT)
// 128x128 CTA tile, BK=16, 8 warps (64x32 warptile), hi/lo interleaved uint2
// smem, double-buffered stages, 1 sync per chunk, 2 CTAs/SM.
// ===========================================================================
__global__ __launch_bounds__(256, 2) void gemm_tf32x3(
    const float* __restrict__ emb, const float* __restrict__ cw) {
    extern __shared__ uint2 smem[];

    const int tid = threadIdx.x;
    const int wid = tid >> 5, lid = tid & 31;
    const int qid = lid >> 2, qlane = lid & 3;
    const int m0 = blockIdx.y * BM, n0 = blockIdx.x * BN;
    const int wm = (wid >> 2) * 64;
    const int wn = (wid & 3) * 32;

    float acc[4][4][4];
#pragma unroll
    for (int mt = 0; mt < 4; mt++)
#pragma unroll
        for (int nt = 0; nt < 4; nt++)
#pragma unroll
            for (int j = 0; j < 4; j++) acc[mt][nt][j] = 0.f;

    const int row_ld = tid >> 2;   // 0..63 (+64 for it=1)
    const int c4_ld  = tid & 3;
    const float4 z4 = make_float4(0.f, 0.f, 0.f, 0.f);
    float4 avA[2], avB[2];

    // ---- prologue: load + stage chunk 0 into buffer 0 ----
#pragma unroll
    for (int it = 0; it < 2; it++) {
        int row = row_ld + it * 64;
        int gm = m0 + row, gn = n0 + row;
        avA[it] = (gm < M_V) ? *(const float4*)(emb + (size_t)gm * K_D + c4_ld * 4) : z4;
        avB[it] = (gn < N_F) ? *(const float4*)(cw + (size_t)gn * K_D + c4_ld * 4) : z4;
    }
#pragma unroll
    for (int it = 0; it < 2; it++) {
        int row = row_ld + it * 64;
        int off = row * LDU2 + c4_ld * 4;
        split_store(smem + off, avA[it]);
        split_store(smem + BM * LDU2 + off, avB[it]);
    }
    __syncthreads();

    for (int c = 0; c < NCHUNK; c++) {
        const uint2* As = smem + (c & 1) * STAGE_U2;
        const uint2* Bs = As + BM * LDU2;
        const bool more = (c + 1 < NCHUNK);

        // issue next chunk's global loads first (latency covered by MMAs)
        if (more) {
#pragma unroll
            for (int it = 0; it < 2; it++) {
                int row = row_ld + it * 64;
                int gk4 = (c + 1) * 4 + c4_ld;
                bool kok = gk4 < 75;          // 300/4 valid float4 columns
                int gm = m0 + row, gn = n0 + row;
                avA[it] = (kok && gm < M_V)
                              ? *(const float4*)(emb + (size_t)gm * K_D + gk4 * 4) : z4;
                avB[it] = (kok && gn < N_F)
                              ? *(const float4*)(cw + (size_t)gn * K_D + gk4 * 4) : z4;
            }
        }

        // ---- compute: 2 k8 steps from current stage ----
#pragma unroll
        for (int kk = 0; kk < 16; kk += 8) {
            uint32_t bh[4][2], bl[4][2];
#pragma unroll
            for (int nt = 0; nt < 4; nt++) {
                int nb = (wn + nt * 8 + qid) * LDU2 + kk + qlane;
                uint2 b0 = Bs[nb], b1 = Bs[nb + 4];
                bh[nt][0] = b0.x; bh[nt][1] = b1.x;
                bl[nt][0] = b0.y; bl[nt][1] = b1.y;
            }
#pragma unroll
            for (int mt = 0; mt < 4; mt++) {
                int ab = (wm + mt * 16 + qid) * LDU2 + kk + qlane;
                uint2 a0 = As[ab], a1 = As[ab + 8 * LDU2];
                uint2 a2 = As[ab + 4], a3 = As[ab + 8 * LDU2 + 4];
                uint32_t ah[4] = {a0.x, a1.x, a2.x, a3.x};
                uint32_t al[4] = {a0.y, a1.y, a2.y, a3.y};
#pragma unroll
                for (int nt = 0; nt < 4; nt++) {
                    mma8(acc[mt][nt], ah, bh[nt]);   // hi*hi
                    mma8(acc[mt][nt], ah, bl[nt]);   // hi*lo
                    mma8(acc[mt][nt], al, bh[nt]);   // lo*hi
                }
            }
        }

        // ---- split + store next chunk into the other stage ----
        if (more) {
            uint2* Ad = smem + ((c + 1) & 1) * STAGE_U2;
            uint2* Bd = Ad + BM * LDU2;
#pragma unroll
            for (int it = 0; it < 2; it++) {
                int row = row_ld + it * 64;
                int off = row * LDU2 + c4_ld * 4;
                split_store(Ad + off, avA[it]);
                split_store(Bd + off, avB[it]);
            }
        }
        __syncthreads();
    }

    // ---- epilogue ----
#pragma unroll
    for (int mt = 0; mt < 4; mt++) {
        int mlo = m0 + wm + mt * 16 + qid;
        int mhi = mlo + 8;
#pragma unroll
        for (int nt = 0; nt < 4; nt++) {
            int n = n0 + wn + nt * 8 + qlane * 2;
            if (n < N_F) {
                if (mlo < M_V)
                    *(float2*)(g_S + (size_t)mlo * N_F + n) =
                        make_float2(acc[mt][nt][0], acc[mt][nt][1]);
                if (mhi < M_V)
                    *(float2*)(g_S + (size_t)mhi * N_F + n) =
                        make_float2(acc[mt][nt][2], acc[mt][nt][3]);
            }
        }
    }
}

// ===========================================================================
// Phase 2 (f-split x2): per (b,f): first-index argmax over t of S[inp[b,t],f];
// val = relu(max + conv_b[f]); contrib = val*(fc_w[1,f]-fc_w[0,f]);
// partial[b,argmax] += contrib (deterministic ordered gather per split).
// ===========================================================================
#define FSPLIT 500
__global__ __launch_bounds__(512) void reduce_scatter2(
    const int* __restrict__ inp, const float* __restrict__ cb,
    const float* __restrict__ fcw) {
    __shared__ int   sw[L_L];
    __shared__ int   sbt[FSPLIT];
    __shared__ float sct[FSPLIT];

    const int b = blockIdx.x;
    const int sp = blockIdx.y;
    const int tid = threadIdx.x;

    sw[tid] = inp[b * L_L + tid];
    __syncthreads();

    if (tid < FSPLIT) {
        const int f = sp * FSPLIT + tid;
        const float* Sf = g_S + f;
        float best = -3.4e38f;
        int bestt = 0;
        for (int t0 = 0; t0 < L_L; t0 += 8) {
            float vv[8];
#pragma unroll
            for (int j = 0; j < 8; j++)
                vv[j] = Sf[(size_t)sw[t0 + j] * N_F];
#pragma unroll
            for (int j = 0; j < 8; j++) {
                if (vv[j] > best) { best = vv[j]; bestt = t0 + j; }  // first-idx
            }
        }
        float val = fmaxf(best + cb[f], 0.f);          // relu(max) == max(relu)
        float contrib = val * (fcw[N_F + f] - fcw[f]); // 0 when val==0 -> idx moot
        sbt[tid] = bestt;
        sct[tid] = contrib;
    }
    __syncthreads();

    float accv = 0.f;
    for (int ff = 0; ff < FSPLIT; ff++) {
        if (sbt[ff] == tid) accv += sct[ff];
    }
    g_P[(sp * B_B + b) * L_L + tid] = accv;
}

__global__ __launch_bounds__(512) void combine(const float* __restrict__ fcb,
                                               float* __restrict__ out) {
    const int b = blockIdx.x;
    const int t = threadIdx.x;
    out[b * L_L + t] = (fcb[1] - fcb[0]) + g_P[b * L_L + t]
                     + g_P[(B_B + b) * L_L + t];
}

extern "C" void kernel_launch(void* const* d_in, const int* in_sizes, int n_in,
                              void* d_out, int out_size) {
    const int*   inp    = (const int*)d_in[0];
    const float* emb    = (const float*)d_in[1];
    const float* conv_w = (const float*)d_in[2];   // [1000,1,300] contiguous
    const float* conv_b = (const float*)d_in[3];
    const float* fc_w   = (const float*)d_in[4];   // [2,1000]
    const float* fc_b   = (const float*)d_in[5];
    float* out = (float*)d_out;

    static int smem_set = 0;
    if (!smem_set) {
        cudaFuncSetAttribute(gemm_tf32x3,
                             cudaFuncAttributeMaxDynamicSharedMemorySize,
                             SMEM_BYTES);
        smem_set = 1;
    }

    dim3 g1(8, 391);   // n-tiles x m-tiles
    gemm_tf32x3<<<g1, 256, SMEM_BYTES>>>(emb, conv_w);
    reduce_scatter2<<<dim3(B_B, 2), 512>>>(inp, conv_b, fc_w);
    combine<<<B_B, 512>>>(fc_b, out);
}

// round 9
// speedup vs baseline: 1.5510x; 1.5510x over previous
#include <cuda_runtime.h>
#include <cuda_fp16.h>
#include <cstdint>

#define M_V 50000   // vocab
#define N_F 1000    // filters
#define K_D 300     // embedding dim
#define B_B 128
#define L_L 512

#define SCALE_IN  128.0f              // 2^7 per operand (keeps lo normal-range)
#define SCALE_OUT (1.0f / 16384.0f)   // 2^-14 on scores

// 200 MB scratch: vocab x filter score table S[v,f] (scaled by 2^14)
__device__ float g_S[(size_t)M_V * N_F];

#define LDP 12                   // uint2 row stride: 8 pairs + 4 pad
#define STAGE_U2 (256 * LDP)     // 128 A rows + 128 B rows = 3072 uint2
#define NCHUNK 19                // ceil(300/16)

// ---------------------------------------------------------------------------
__device__ __forceinline__ uint32_t h2u(half2 h) {
    return *reinterpret_cast<const uint32_t*>(&h);
}

__device__ __forceinline__ void mma16(float* c, const uint32_t* a, const uint32_t* b) {
    asm volatile(
        "mma.sync.aligned.m16n8k16.row.col.f32.f16.f16.f32 "
        "{%0,%1,%2,%3}, {%4,%5,%6,%7}, {%8,%9}, {%0,%1,%2,%3};"
        : "+f"(c[0]), "+f"(c[1]), "+f"(c[2]), "+f"(c[3])
        : "r"(a[0]), "r"(a[1]), "r"(a[2]), "r"(a[3]), "r"(b[0]), "r"(b[1]));
}

// scale by 2^7, split each float into fp16 hi + fp16 lo(residual), store
// 2 pairs: dst[0] = (h2(x0,x1), l2(x0,x1)), dst[1] = (h2(x2,x3), l2(x2,x3)).
// Low half of each uint32 = even-k element (fragment order).
__device__ __forceinline__ void split_store(uint2* dst, float4 v) {
    float x0 = v.x * SCALE_IN, x1 = v.y * SCALE_IN;
    float x2 = v.z * SCALE_IN, x3 = v.w * SCALE_IN;
    half2 h01 = __floats2half2_rn(x0, x1);
    half2 h23 = __floats2half2_rn(x2, x3);
    float2 f01 = __half22float2(h01);
    float2 f23 = __half22float2(h23);
    half2 l01 = __floats2half2_rn(x0 - f01.x, x1 - f01.y);
    half2 l23 = __floats2half2_rn(x2 - f23.x, x3 - f23.y);
    uint4 o = make_uint4(h2u(h01), h2u(l01), h2u(h23), h2u(l23));
    *(uint4*)dst = o;
}

// ===========================================================================
// Phase 1: S = Ah.Bh + Ah.Bl + Al.Bh  via fp16 m16n8k16 mma.sync (NT)
// 128x128 CTA tile, BK=16 floats (1 k16-step, 19 chunks), 8 warps (64x32
// warptile), in-loop split (R4-proven skeleton), double-staged static smem.
// ===========================================================================
__global__ __launch_bounds__(256) void gemm_fp16x3(
    const float* __restrict__ emb, const float* __restrict__ cw) {
    __shared__ uint2 sm[2 * STAGE_U2];   // 49152 bytes

    const int tid = threadIdx.x;
    const int wid = tid >> 5, lid = tid & 31;
    const int qid = lid >> 2, ql = lid & 3;
    const int m0 = blockIdx.y * 128, n0 = blockIdx.x * 128;
    const int wm = (wid >> 2) * 64, wn = (wid & 3) * 32;

    float acc[4][4][4];
#pragma unroll
    for (int mt = 0; mt < 4; mt++)
#pragma unroll
        for (int nt = 0; nt < 4; nt++)
#pragma unroll
            for (int j = 0; j < 4; j++) acc[mt][nt][j] = 0.f;

    const int row_ld = tid >> 2;     // 0..63 (+64 for it=1)
    const int c4_ld  = tid & 3;      // float4 column within chunk
    const float4 z4 = make_float4(0.f, 0.f, 0.f, 0.f);
    float4 avA[2], avB[2];

    // ---- prologue: load chunk 0, stage into buffer 0 ----
#pragma unroll
    for (int it = 0; it < 2; it++) {
        int row = row_ld + it * 64;
        int gm = m0 + row, gn = n0 + row;
        avA[it] = (gm < M_V) ? *(const float4*)(emb + (size_t)gm * K_D + c4_ld * 4) : z4;
        avB[it] = (gn < N_F) ? *(const float4*)(cw + (size_t)gn * K_D + c4_ld * 4) : z4;
    }
#pragma unroll
    for (int it = 0; it < 2; it++) {
        int row = row_ld + it * 64;
        int off = row * LDP + c4_ld * 2;
        split_store(sm + off, avA[it]);                  // A region
        split_store(sm + 128 * LDP + off, avB[it]);      // B region
    }
    __syncthreads();

    for (int c = 0; c < NCHUNK; c++) {
        const uint2* As = sm + (c & 1) * STAGE_U2;
        const uint2* Bs = As + 128 * LDP;
        const bool more = (c + 1 < NCHUNK);

        // prefetch next chunk (latency hidden by MMAs below)
        if (more) {
#pragma unroll
            for (int it = 0; it < 2; it++) {
                int row = row_ld + it * 64;
                int gk4 = (c + 1) * 4 + c4_ld;
                bool kok = gk4 < 75;          // 300/4 valid float4 columns
                int gm = m0 + row, gn = n0 + row;
                avA[it] = (kok && gm < M_V)
                              ? *(const float4*)(emb + (size_t)gm * K_D + gk4 * 4) : z4;
                avB[it] = (kok && gn < N_F)
                              ? *(const float4*)(cw + (size_t)gn * K_D + gk4 * 4) : z4;
            }
        }

        // ---- compute: one m16n8k16 step per (mt,nt) per pass ----
        uint32_t bh[4][2], bl[4][2];
#pragma unroll
        for (int nt = 0; nt < 4; nt++) {
            const uint2* p = Bs + (wn + nt * 8 + qid) * LDP + ql;
            uint2 b0 = p[0], b1 = p[4];      // pairs ql, ql+4 (k=2ql.., 2ql+8..)
            bh[nt][0] = b0.x; bh[nt][1] = b1.x;
            bl[nt][0] = b0.y; bl[nt][1] = b1.y;
        }
#pragma unroll
        for (int mt = 0; mt < 4; mt++) {
            const uint2* pa = As + (wm + mt * 16 + qid) * LDP + ql;
            uint2 a0 = pa[0], a1 = pa[8 * LDP];       // rows r, r+8 @ pair ql
            uint2 a2 = pa[4], a3 = pa[8 * LDP + 4];   // rows r, r+8 @ pair ql+4
            uint32_t ah[4] = {a0.x, a1.x, a2.x, a3.x};
            uint32_t al[4] = {a0.y, a1.y, a2.y, a3.y};
#pragma unroll
            for (int nt = 0; nt < 4; nt++) {
                mma16(acc[mt][nt], ah, bh[nt]);   // hi*hi
                mma16(acc[mt][nt], ah, bl[nt]);   // hi*lo
                mma16(acc[mt][nt], al, bh[nt]);   // lo*hi
            }
        }

        // ---- split + store next chunk into the other stage ----
        if (more) {
            uint2* Ad = sm + ((c + 1) & 1) * STAGE_U2;
            uint2* Bd = Ad + 128 * LDP;
#pragma unroll
            for (int it = 0; it < 2; it++) {
                int row = row_ld + it * 64;
                int off = row * LDP + c4_ld * 2;
                split_store(Ad + off, avA[it]);
                split_store(Bd + off, avB[it]);
            }
        }
        __syncthreads();
    }

    // ---- epilogue (scores scaled by 2^14; phase 2 descales) ----
#pragma unroll
    for (int mt = 0; mt < 4; mt++) {
        int mlo = m0 + wm + mt * 16 + qid;
        int mhi = mlo + 8;
#pragma unroll
        for (int nt = 0; nt < 4; nt++) {
            int n = n0 + wn + nt * 8 + ql * 2;
            if (n < N_F) {
                if (mlo < M_V)
                    *(float2*)(g_S + (size_t)mlo * N_F + n) =
                        make_float2(acc[mt][nt][0], acc[mt][nt][1]);
                if (mhi < M_V)
                    *(float2*)(g_S + (size_t)mhi * N_F + n) =
                        make_float2(acc[mt][nt][2], acc[mt][nt][3]);
            }
        }
    }
}

// ===========================================================================
// Phase 2: per (b,f): first-index argmax over t of S[inp[b,t],f] (scaled
// scores: argmax invariant); val = relu(2^-14*max + conv_b[f]);
// contrib = val*(fc_w[1,f]-fc_w[0,f]); token[b,argmax] += contrib;
// token += fc_b[1]-fc_b[0]. Deterministic ordered gather.
// ===========================================================================
__global__ __launch_bounds__(1024) void reduce_scatter(
    const int* __restrict__ inp, const float* __restrict__ cb,
    const float* __restrict__ fcw, const float* __restrict__ fcb,
    float* __restrict__ out) {
    __shared__ int   sw[L_L];
    __shared__ int   sbt[N_F];
    __shared__ float sct[N_F];

    const int b = blockIdx.x;
    const int tid = threadIdx.x;

    if (tid < L_L) sw[tid] = inp[b * L_L + tid];
    __syncthreads();

    const int f = tid;
    if (f < N_F) {
        const float* Sf = g_S + f;
        float best = -3.4e38f;
        int bestt = 0;
        for (int t0 = 0; t0 < L_L; t0 += 8) {
            float vv[8];
#pragma unroll
            for (int j = 0; j < 8; j++)
                vv[j] = Sf[(size_t)sw[t0 + j] * N_F];
#pragma unroll
            for (int j = 0; j < 8; j++) {
                if (vv[j] > best) { best = vv[j]; bestt = t0 + j; }  // first idx
            }
        }
        float val = fmaxf(best * SCALE_OUT + cb[f], 0.f);  // descale, relu
        float contrib = val * (fcw[N_F + f] - fcw[f]);     // 0 when val==0
        sbt[f] = bestt;
        sct[f] = contrib;
    }
    __syncthreads();

    if (tid < L_L) {
        float accv = fcb[1] - fcb[0];
        for (int ff = 0; ff < N_F; ff++) {
            if (sbt[ff] == tid) accv += sct[ff];
        }
        out[b * L_L + tid] = accv;
    }
}

extern "C" void kernel_launch(void* const* d_in, const int* in_sizes, int n_in,
                              void* d_out, int out_size) {
    const int*   inp    = (const int*)d_in[0];
    const float* emb    = (const float*)d_in[1];
    const float* conv_w = (const float*)d_in[2];   // [1000,1,300] contiguous
    const float* conv_b = (const float*)d_in[3];
    const float* fc_w   = (const float*)d_in[4];   // [2,1000]
    const float* fc_b   = (const float*)d_in[5];
    float* out = (float*)d_out;

    gemm_fp16x3<<<dim3(8, 391), 256>>>(emb, conv_w);
    reduce_scatter<<<B_B, 1024>>>(inp, conv_b, fc_w, fc_b, out);
}